// round 13
// baseline (speedup 1.0000x reference)
#include <cuda_runtime.h>
#include <cuda_bf16.h>
#include <math.h>
#include <stdint.h>

#define FDIM 256
#define H 128
#define NMAX 50000
#define EMAX 1600000

// Scratch (allocation-free rule: __device__ globals)
#define BUF0_OFF 0
#define BUF1_OFF (NMAX * H)
#define BUF2_OFF (2 * NMAX * H)
__device__ float g_scratch[3 * NMAX * H];
__device__ float g_dis[NMAX];
__device__ int   g_cnt[NMAX];
__device__ int   g_fill[NMAX];
__device__ int   g_rowptr[NMAX + 1];
__device__ int   g_csr_src[EMAX];
__device__ float g_csr_norm[EMAX];
__device__ int   g_blocksum[64];
__device__ int   g_blockoff[64];

__device__ __forceinline__ const float* rsv(const float* p, int off) {
    return p ? p : (g_scratch + off);
}

__device__ __forceinline__ float4 ldbf4(const __nv_bfloat16* p) {
    uint2 u = *(const uint2*)p;
    __nv_bfloat162 h0 = *reinterpret_cast<const __nv_bfloat162*>(&u.x);
    __nv_bfloat162 h1 = *reinterpret_cast<const __nv_bfloat162*>(&u.y);
    float2 f0 = __bfloat1622float2(h0);
    float2 f1 = __bfloat1622float2(h1);
    return make_float4(f0.x, f0.y, f1.x, f1.y);
}

// ---------------------------------------------------------------------------
// CSR build: count -> dis -> 3-phase scan -> fill
// ---------------------------------------------------------------------------
__global__ void zero_int_kernel(int n) {
    int i = blockIdx.x * blockDim.x + threadIdx.x;
    if (i < n) { g_cnt[i] = 0; g_fill[i] = 0; }
}

__global__ void count_kernel(const int* __restrict__ ei, int E) {
    int e = blockIdx.x * blockDim.x + threadIdx.x;
    if (e < E) atomicAdd(&g_cnt[ei[(size_t)E + e]], 1);
}

__global__ void dis_kernel(int n) {
    int i = blockIdx.x * blockDim.x + threadIdx.x;
    if (i < n) g_dis[i] = rsqrtf((float)(g_cnt[i] + 1));  // +1 self loop
}

__global__ void scan_phase1(int n) {
    int t = threadIdx.x;
    int base = blockIdx.x * 1024 + t * 4;
    int s = 0;
#pragma unroll
    for (int j = 0; j < 4; j++) { int i = base + j; if (i < n) s += g_cnt[i]; }
#pragma unroll
    for (int off = 16; off; off >>= 1) s += __shfl_xor_sync(0xffffffffu, s, off);
    __shared__ int wsum[8];
    if ((t & 31) == 0) wsum[t >> 5] = s;
    __syncthreads();
    if (t == 0) {
        int tot = 0;
#pragma unroll
        for (int w = 0; w < 8; w++) tot += wsum[w];
        g_blocksum[blockIdx.x] = tot;
    }
}

__global__ void scan_phase2(int nb) {
    __shared__ int sh[64];
    int t = threadIdx.x;
    int v = (t < nb) ? g_blocksum[t] : 0;
    sh[t] = v;
    __syncthreads();
    for (int off = 1; off < 64; off <<= 1) {
        int tmp = (t >= off) ? sh[t - off] : 0;
        __syncthreads();
        sh[t] += tmp;
        __syncthreads();
    }
    if (t < nb) g_blockoff[t] = sh[t] - v;  // exclusive
}

__global__ void scan_phase3(int n, int E) {
    int t = threadIdx.x;
    int base = blockIdx.x * 1024 + t * 4;
    int v[4]; int s = 0;
#pragma unroll
    for (int j = 0; j < 4; j++) { int i = base + j; v[j] = (i < n) ? g_cnt[i] : 0; s += v[j]; }
    int incl = s;
#pragma unroll
    for (int off = 1; off < 32; off <<= 1) {
        int tmp = __shfl_up_sync(0xffffffffu, incl, off);
        if ((t & 31) >= off) incl += tmp;
    }
    __shared__ int wtot[8];
    __shared__ int woff[8];
    if ((t & 31) == 31) wtot[t >> 5] = incl;
    __syncthreads();
    if (t < 8) {
        int wv = wtot[t];
        int wincl = wv;
#pragma unroll
        for (int off = 1; off < 8; off <<= 1) {
            int tmp = __shfl_up_sync(0x000000ffu, wincl, off);
            if (t >= off) wincl += tmp;
        }
        woff[t] = wincl - wv;
    }
    __syncthreads();
    int prefix = g_blockoff[blockIdx.x] + woff[t >> 5] + (incl - s);
#pragma unroll
    for (int j = 0; j < 4; j++) {
        int i = base + j;
        if (i < n) g_rowptr[i] = prefix;
        prefix += v[j];
    }
    if (blockIdx.x == 0 && t == 0) g_rowptr[n] = E;
}

__global__ void fill_kernel(const int* __restrict__ ei, int E) {
    int e = blockIdx.x * blockDim.x + threadIdx.x;
    if (e >= E) return;
    int s = ei[e];
    int d = ei[(size_t)E + e];
    int pos = g_rowptr[d] + atomicAdd(&g_fill[d], 1);
    g_csr_src[pos] = s;
    g_csr_norm[pos] = g_dis[s] * g_dis[d];
}

// ---------------------------------------------------------------------------
// bf16 mma.sync GEMM (m16n8k16, fp32 accum). N fixed to 128.
// Block 128x128, BK=32, 256 threads = 8 warps (2m x 4n), warp tile 64x32.
// OBF: write output as bf16 (for edge-gathered buffers).
// ---------------------------------------------------------------------------
#define ASTRIDE 40  // bf16 elements per smem row (80 bytes)

__device__ __forceinline__ unsigned cvt2(float x, float y) {
    __nv_bfloat162 h = __floats2bfloat162_rn(x, y);
    return *reinterpret_cast<unsigned*>(&h);
}

template <bool RIN, bool ROUT, bool BIAS, bool OBF>
__global__ __launch_bounds__(256)
void gemm_bf16(const float* __restrict__ Aext, int aOff,
               const float* __restrict__ W,
               const float* __restrict__ bias,
               int cOff, int M, int K) {
    const float* A = rsv(Aext, aOff);
    float* C = g_scratch + cOff;
    __nv_bfloat16* Cb = (__nv_bfloat16*)(g_scratch + cOff);

    __shared__ __align__(16) __nv_bfloat16 sA[128 * ASTRIDE];
    __shared__ __align__(16) __nv_bfloat16 sB[128 * ASTRIDE];

    const int tid = threadIdx.x;
    const int lane = tid & 31;
    const int wid = tid >> 5;
    const int warp_m = wid >> 2;        // 0..1
    const int warp_n = wid & 3;         // 0..3
    const int g = lane >> 2;            // 0..7
    const int tig = lane & 3;           // 0..3
    const int rowBase = blockIdx.x * 128;

    float acc[4][4][4];
#pragma unroll
    for (int mt = 0; mt < 4; mt++)
#pragma unroll
        for (int nt = 0; nt < 4; nt++)
#pragma unroll
            for (int r = 0; r < 4; r++) acc[mt][nt][r] = 0.0f;

    // staging roles
    const int srow = tid >> 1;          // A row / B n (0..127)
    const int shalf = tid & 1;          // col half (16 elements)
    const int aRow = rowBase + srow;
    const bool aValid = (aRow < M);
    const float* aPtr = A + (size_t)aRow * K + shalf * 16;

    // ldmatrix lane addressing
    const int q = lane >> 3;            // quadrant
    const int lr = lane & 7;
    const int arow_l = lr + 8 * (q & 1);        // row within 16
    const int acolB = (q >> 1) * 16;            // byte offset within kstep
    const int brow_l = lr + 8 * (q >> 1);       // n within 16
    const int bcolB = (q & 1) * 16;             // k-half byte offset

    const int nTile = K >> 5;
    for (int kt = 0; kt < nTile; kt++) {
        const int k0 = kt << 5;
        // ---- stage A ----
        {
            float4 v0 = make_float4(0,0,0,0), v1 = v0, v2 = v0, v3 = v0;
            if (aValid) {
                const float4* p = (const float4*)(aPtr + k0);
                v0 = p[0]; v1 = p[1]; v2 = p[2]; v3 = p[3];
                if (RIN) {
                    v0.x=fmaxf(v0.x,0.f); v0.y=fmaxf(v0.y,0.f); v0.z=fmaxf(v0.z,0.f); v0.w=fmaxf(v0.w,0.f);
                    v1.x=fmaxf(v1.x,0.f); v1.y=fmaxf(v1.y,0.f); v1.z=fmaxf(v1.z,0.f); v1.w=fmaxf(v1.w,0.f);
                    v2.x=fmaxf(v2.x,0.f); v2.y=fmaxf(v2.y,0.f); v2.z=fmaxf(v2.z,0.f); v2.w=fmaxf(v2.w,0.f);
                    v3.x=fmaxf(v3.x,0.f); v3.y=fmaxf(v3.y,0.f); v3.z=fmaxf(v3.z,0.f); v3.w=fmaxf(v3.w,0.f);
                }
            }
            uint4 u0, u1;
            u0.x = cvt2(v0.x, v0.y); u0.y = cvt2(v0.z, v0.w);
            u0.z = cvt2(v1.x, v1.y); u0.w = cvt2(v1.z, v1.w);
            u1.x = cvt2(v2.x, v2.y); u1.y = cvt2(v2.z, v2.w);
            u1.z = cvt2(v3.x, v3.y); u1.w = cvt2(v3.z, v3.w);
            uint4* dst = (uint4*)(sA + srow * ASTRIDE + shalf * 16);
            dst[0] = u0; dst[1] = u1;
        }
        // ---- stage B (transpose W) ----
        {
            const float* wp = W + (size_t)(k0 + shalf * 16) * 128 + srow;
            float w[16];
#pragma unroll
            for (int j = 0; j < 16; j++) w[j] = wp[(size_t)j * 128];
            uint4 u0, u1;
            u0.x = cvt2(w[0], w[1]);   u0.y = cvt2(w[2], w[3]);
            u0.z = cvt2(w[4], w[5]);   u0.w = cvt2(w[6], w[7]);
            u1.x = cvt2(w[8], w[9]);   u1.y = cvt2(w[10], w[11]);
            u1.z = cvt2(w[12], w[13]); u1.w = cvt2(w[14], w[15]);
            uint4* dst = (uint4*)(sB + srow * ASTRIDE + shalf * 16);
            dst[0] = u0; dst[1] = u1;
        }
        __syncthreads();

        // ---- compute ----
#pragma unroll
        for (int ks = 0; ks < 2; ks++) {
            uint32_t af[4][4];
#pragma unroll
            for (int mt = 0; mt < 4; mt++) {
                const __nv_bfloat16* p = sA + (warp_m * 64 + mt * 16 + arow_l) * ASTRIDE + ks * 16;
                uint32_t addr = (uint32_t)__cvta_generic_to_shared(p) + acolB;
                asm volatile("ldmatrix.sync.aligned.m8n8.x4.shared.b16 {%0,%1,%2,%3}, [%4];"
                             : "=r"(af[mt][0]), "=r"(af[mt][1]), "=r"(af[mt][2]), "=r"(af[mt][3])
                             : "r"(addr));
            }
            uint32_t bf[4][2];
#pragma unroll
            for (int np = 0; np < 2; np++) {
                const __nv_bfloat16* p = sB + (warp_n * 32 + np * 16 + brow_l) * ASTRIDE + ks * 16;
                uint32_t addr = (uint32_t)__cvta_generic_to_shared(p) + bcolB;
                uint32_t r0, r1, r2, r3;
                asm volatile("ldmatrix.sync.aligned.m8n8.x4.shared.b16 {%0,%1,%2,%3}, [%4];"
                             : "=r"(r0), "=r"(r1), "=r"(r2), "=r"(r3)
                             : "r"(addr));
                bf[np * 2][0] = r0;     bf[np * 2][1] = r1;
                bf[np * 2 + 1][0] = r2; bf[np * 2 + 1][1] = r3;
            }
#pragma unroll
            for (int mt = 0; mt < 4; mt++)
#pragma unroll
                for (int nt = 0; nt < 4; nt++) {
                    asm volatile(
                        "mma.sync.aligned.m16n8k16.row.col.f32.bf16.bf16.f32 "
                        "{%0,%1,%2,%3}, {%4,%5,%6,%7}, {%8,%9}, {%0,%1,%2,%3};"
                        : "+f"(acc[mt][nt][0]), "+f"(acc[mt][nt][1]),
                          "+f"(acc[mt][nt][2]), "+f"(acc[mt][nt][3])
                        : "r"(af[mt][0]), "r"(af[mt][1]), "r"(af[mt][2]), "r"(af[mt][3]),
                          "r"(bf[nt][0]), "r"(bf[nt][1]));
                }
        }
        __syncthreads();
    }

    // ---- epilogue ----
#pragma unroll
    for (int mt = 0; mt < 4; mt++) {
        int row0 = rowBase + warp_m * 64 + mt * 16 + g;
#pragma unroll
        for (int nt = 0; nt < 4; nt++) {
            int col = warp_n * 32 + nt * 8 + tig * 2;
            float b0 = 0.f, b1 = 0.f;
            if (BIAS) { b0 = bias[col]; b1 = bias[col + 1]; }
            float2 v01, v23;
            v01.x = acc[mt][nt][0] + b0; v01.y = acc[mt][nt][1] + b1;
            v23.x = acc[mt][nt][2] + b0; v23.y = acc[mt][nt][3] + b1;
            if (ROUT) {
                v01.x = fmaxf(v01.x, 0.f); v01.y = fmaxf(v01.y, 0.f);
                v23.x = fmaxf(v23.x, 0.f); v23.y = fmaxf(v23.y, 0.f);
            }
            if (OBF) {
                if (row0 < M) {
                    __nv_bfloat162 h = __floats2bfloat162_rn(v01.x, v01.y);
                    *(__nv_bfloat162*)(Cb + (size_t)row0 * 128 + col) = h;
                }
                if (row0 + 8 < M) {
                    __nv_bfloat162 h = __floats2bfloat162_rn(v23.x, v23.y);
                    *(__nv_bfloat162*)(Cb + (size_t)(row0 + 8) * 128 + col) = h;
                }
            } else {
                if (row0 < M)     *(float2*)(C + (size_t)row0 * 128 + col) = v01;
                if (row0 + 8 < M) *(float2*)(C + (size_t)(row0 + 8) * 128 + col) = v23;
            }
        }
    }
}

// ---------------------------------------------------------------------------
// GCN aggregation (gather, no atomics): one warp per dst node.
// Reads bf16 xw rows, accumulates fp32, writes fp32.
// ---------------------------------------------------------------------------
__global__ __launch_bounds__(256)
void aggregate_kernel(int xwOff, const float* __restrict__ bias,
                      int outOff, int n) {
    const __nv_bfloat16* xw = (const __nv_bfloat16*)(g_scratch + xwOff);
    float4* out4 = (float4*)(g_scratch + outOff);
    int d = (blockIdx.x * blockDim.x + threadIdx.x) >> 5;
    int lane = threadIdx.x & 31;
    if (d >= n) return;

    const int c = lane * 4;
    float di = g_dis[d];
    float sn = di * di;
    float4 b = ((const float4*)bias)[lane];
    float4 x = ldbf4(xw + (size_t)d * H + c);
    float4 acc;
    acc.x = b.x + sn * x.x; acc.y = b.y + sn * x.y;
    acc.z = b.z + sn * x.z; acc.w = b.w + sn * x.w;

    int i = g_rowptr[d];
    const int end = g_rowptr[d + 1];
    for (; i + 1 < end; i += 2) {
        int s0 = g_csr_src[i], s1 = g_csr_src[i + 1];
        float n0 = g_csr_norm[i], n1 = g_csr_norm[i + 1];
        float4 v0 = ldbf4(xw + (size_t)s0 * H + c);
        float4 v1 = ldbf4(xw + (size_t)s1 * H + c);
        acc.x += n0 * v0.x + n1 * v1.x;
        acc.y += n0 * v0.y + n1 * v1.y;
        acc.z += n0 * v0.z + n1 * v1.z;
        acc.w += n0 * v0.w + n1 * v1.w;
    }
    if (i < end) {
        int s0 = g_csr_src[i];
        float n0 = g_csr_norm[i];
        float4 v0 = ldbf4(xw + (size_t)s0 * H + c);
        acc.x += n0 * v0.x; acc.y += n0 * v0.y;
        acc.z += n0 * v0.z; acc.w += n0 * v0.w;
    }
    out4[(size_t)d * 32 + lane] = acc;
}

// ---------------------------------------------------------------------------
// Edge classifier: out[e] = sigmoid( dot(relu(A[src]+B[dst]), w2) + b2 )
// A,B are bf16 rows.
// ---------------------------------------------------------------------------
__global__ void edge_cls_kernel(const int* __restrict__ ei,
                                int aOff, int bOff,
                                const float* __restrict__ w2,
                                const float* __restrict__ b2,
                                float* __restrict__ out, int E) {
    const __nv_bfloat16* Amat = (const __nv_bfloat16*)(g_scratch + aOff);
    const __nv_bfloat16* Bmat = (const __nv_bfloat16*)(g_scratch + bOff);
    int w = (blockIdx.x * blockDim.x + threadIdx.x) >> 5;
    int lane = threadIdx.x & 31;
    if (w >= E) return;
    int s = ei[w];
    int d = ei[(size_t)E + w];
    const int c = lane * 4;
    float4 a = ldbf4(Amat + (size_t)s * H + c);
    float4 b = ldbf4(Bmat + (size_t)d * H + c);
    float4 ww = ((const float4*)w2)[lane];
    float p = fmaxf(a.x + b.x, 0.f) * ww.x
            + fmaxf(a.y + b.y, 0.f) * ww.y
            + fmaxf(a.z + b.z, 0.f) * ww.z
            + fmaxf(a.w + b.w, 0.f) * ww.w;
#pragma unroll
    for (int off = 16; off; off >>= 1)
        p += __shfl_xor_sync(0xffffffffu, p, off);
    if (lane == 0) {
        float z = p + b2[0];
        out[w] = 1.0f / (1.0f + __expf(-z));
    }
}

// ---------------------------------------------------------------------------
extern "C" void kernel_launch(void* const* d_in, const int* in_sizes, int n_in,
                              void* d_out, int out_size) {
    const float* nf      = (const float*)d_in[0];
    const int*   ei      = (const int*)d_in[1];
    const float* enc_w1  = (const float*)d_in[2];
    const float* enc_b1  = (const float*)d_in[3];
    const float* enc_w2  = (const float*)d_in[4];
    const float* enc_b2  = (const float*)d_in[5];
    const float* conv_w1 = (const float*)d_in[6];
    const float* conv_b1 = (const float*)d_in[7];
    const float* conv_w2 = (const float*)d_in[8];
    const float* conv_b2 = (const float*)d_in[9];
    const float* conv_w3 = (const float*)d_in[10];
    const float* conv_b3 = (const float*)d_in[11];
    const float* cls_w1  = (const float*)d_in[12];
    const float* cls_b1  = (const float*)d_in[13];
    const float* cls_w2  = (const float*)d_in[14];
    const float* cls_b2  = (const float*)d_in[15];

    const int n = in_sizes[0] / FDIM;
    const int E = in_sizes[1] / 2;

    const int T = 256;
    const int gm = (n + 127) / 128;
    const int gN = (n + T - 1) / T;
    const int gE = (E + T - 1) / T;
    const int gAgg = (n * 32 + T - 1) / T;
    const int nb = (n + 1023) / 1024;
    const long long eThreads = (long long)E * 32;
    const int gEdge = (int)((eThreads + T - 1) / T);

    // CSR build + normalization
    zero_int_kernel<<<gN, T>>>(n);
    count_kernel<<<gE, T>>>(ei, E);
    dis_kernel<<<gN, T>>>(n);
    scan_phase1<<<nb, 256>>>(n);
    scan_phase2<<<1, 64>>>(nb);
    scan_phase3<<<nb, 256>>>(n, E);
    fill_kernel<<<gE, T>>>(ei, E);

    // node encoder: buf1 = relu(nf@W1+b1e)@W2 + b2e   (fp32 buffers)
    gemm_bf16<false, true, true, false><<<gm, 256>>>(nf, 0, enc_w1, enc_b1, BUF0_OFF, n, FDIM);
    gemm_bf16<false, false, true, false><<<gm, 256>>>(nullptr, BUF0_OFF, enc_w2, enc_b2, BUF1_OFF, n, H);

    // conv1: xw bf16 -> BUF0; aggregate -> BUF2 (fp32)
    gemm_bf16<false, false, false, true><<<gm, 256>>>(nullptr, BUF1_OFF, conv_w1, nullptr, BUF0_OFF, n, H);
    aggregate_kernel<<<gAgg, T>>>(BUF0_OFF, conv_b1, BUF2_OFF, n);

    // conv2: input relu(BUF2); xw bf16 -> BUF0; aggregate -> BUF1 (fp32)
    gemm_bf16<true, false, false, true><<<gm, 256>>>(nullptr, BUF2_OFF, conv_w2, nullptr, BUF0_OFF, n, H);
    aggregate_kernel<<<gAgg, T>>>(BUF0_OFF, conv_b2, BUF1_OFF, n);

    // conv3: input relu(BUF1); xw bf16 -> BUF0; aggregate -> BUF2 (fp32)
    gemm_bf16<true, false, false, true><<<gm, 256>>>(nullptr, BUF1_OFF, conv_w3, nullptr, BUF0_OFF, n, H);
    aggregate_kernel<<<gAgg, T>>>(BUF0_OFF, conv_b3, BUF2_OFF, n);

    // classifier partials (bf16): A = X@W1_top + cls_b1 -> BUF0, B = X@W1_bot -> BUF1
    gemm_bf16<false, false, true, true><<<gm, 256>>>(nullptr, BUF2_OFF, cls_w1, cls_b1, BUF0_OFF, n, H);
    gemm_bf16<false, false, false, true><<<gm, 256>>>(nullptr, BUF2_OFF, cls_w1 + 128 * 128, nullptr, BUF1_OFF, n, H);

    // per-edge score
    edge_cls_kernel<<<gEdge, T>>>(ei, BUF0_OFF, BUF1_OFF, cls_w2, cls_b2, (float*)d_out, E);
}

// round 16
// speedup vs baseline: 1.6564x; 1.6564x over previous
#include <cuda_runtime.h>
#include <cuda_bf16.h>
#include <math.h>
#include <stdint.h>

#define FDIM 256
#define H 128
#define NMAX 50000
#define EMAX 1600000

// Scratch (allocation-free rule: __device__ globals)
#define BUF0_OFF 0
#define BUF1_OFF (NMAX * H)
#define BUF2_OFF (2 * NMAX * H)
__device__ float g_scratch[3 * NMAX * H];
__device__ float g_dis[NMAX];
__device__ int   g_cnt[NMAX];
__device__ int   g_fill[NMAX];
__device__ int   g_rowptr[NMAX + 1];
__device__ int   g_csr_src[EMAX];
__device__ int   g_csr_eid[EMAX];
__device__ float g_csr_norm[EMAX];
__device__ int   g_blocksum[64];
__device__ int   g_blockoff[64];

__device__ __forceinline__ const float* rsv(const float* p, int off) {
    return p ? p : (g_scratch + off);
}

// ---------------------------------------------------------------------------
// CSR build: count -> dis -> 3-phase scan -> fill
// ---------------------------------------------------------------------------
__global__ void zero_int_kernel(int n) {
    int i = blockIdx.x * blockDim.x + threadIdx.x;
    if (i < n) { g_cnt[i] = 0; g_fill[i] = 0; }
}

__global__ void count_kernel(const int* __restrict__ ei, int E) {
    int e = blockIdx.x * blockDim.x + threadIdx.x;
    if (e < E) atomicAdd(&g_cnt[ei[(size_t)E + e]], 1);
}

__global__ void dis_kernel(int n) {
    int i = blockIdx.x * blockDim.x + threadIdx.x;
    if (i < n) g_dis[i] = rsqrtf((float)(g_cnt[i] + 1));  // +1 self loop
}

__global__ void scan_phase1(int n) {
    int t = threadIdx.x;
    int base = blockIdx.x * 1024 + t * 4;
    int s = 0;
#pragma unroll
    for (int j = 0; j < 4; j++) { int i = base + j; if (i < n) s += g_cnt[i]; }
#pragma unroll
    for (int off = 16; off; off >>= 1) s += __shfl_xor_sync(0xffffffffu, s, off);
    __shared__ int wsum[8];
    if ((t & 31) == 0) wsum[t >> 5] = s;
    __syncthreads();
    if (t == 0) {
        int tot = 0;
#pragma unroll
        for (int w = 0; w < 8; w++) tot += wsum[w];
        g_blocksum[blockIdx.x] = tot;
    }
}

__global__ void scan_phase2(int nb) {
    __shared__ int sh[64];
    int t = threadIdx.x;
    int v = (t < nb) ? g_blocksum[t] : 0;
    sh[t] = v;
    __syncthreads();
    for (int off = 1; off < 64; off <<= 1) {
        int tmp = (t >= off) ? sh[t - off] : 0;
        __syncthreads();
        sh[t] += tmp;
        __syncthreads();
    }
    if (t < nb) g_blockoff[t] = sh[t] - v;  // exclusive
}

__global__ void scan_phase3(int n, int E) {
    int t = threadIdx.x;
    int base = blockIdx.x * 1024 + t * 4;
    int v[4]; int s = 0;
#pragma unroll
    for (int j = 0; j < 4; j++) { int i = base + j; v[j] = (i < n) ? g_cnt[i] : 0; s += v[j]; }
    int incl = s;
#pragma unroll
    for (int off = 1; off < 32; off <<= 1) {
        int tmp = __shfl_up_sync(0xffffffffu, incl, off);
        if ((t & 31) >= off) incl += tmp;
    }
    __shared__ int wtot[8];
    __shared__ int woff[8];
    if ((t & 31) == 31) wtot[t >> 5] = incl;
    __syncthreads();
    if (t < 8) {
        int wv = wtot[t];
        int wincl = wv;
#pragma unroll
        for (int off = 1; off < 8; off <<= 1) {
            int tmp = __shfl_up_sync(0x000000ffu, wincl, off);
            if (t >= off) wincl += tmp;
        }
        woff[t] = wincl - wv;
    }
    __syncthreads();
    int prefix = g_blockoff[blockIdx.x] + woff[t >> 5] + (incl - s);
#pragma unroll
    for (int j = 0; j < 4; j++) {
        int i = base + j;
        if (i < n) g_rowptr[i] = prefix;
        prefix += v[j];
    }
    if (blockIdx.x == 0 && t == 0) g_rowptr[n] = E;
}

__global__ void fill_kernel(const int* __restrict__ ei, int E) {
    int e = blockIdx.x * blockDim.x + threadIdx.x;
    if (e >= E) return;
    int s = ei[e];
    int d = ei[(size_t)E + e];
    int pos = g_rowptr[d] + atomicAdd(&g_fill[d], 1);
    g_csr_src[pos] = s;
    g_csr_eid[pos] = e;
    g_csr_norm[pos] = g_dis[s] * g_dis[d];
}

// ---------------------------------------------------------------------------
// bf16 mma.sync GEMM (m16n8k16, fp32 accum). N fixed to 128.
// Block 128x128, BK=32, 256 threads = 8 warps (2m x 4n), warp tile 64x32.
// ---------------------------------------------------------------------------
#define ASTRIDE 40  // bf16 elements per smem row (80 bytes)

__device__ __forceinline__ unsigned cvt2(float x, float y) {
    __nv_bfloat162 h = __floats2bfloat162_rn(x, y);
    return *reinterpret_cast<unsigned*>(&h);
}

template <bool RIN, bool ROUT, bool BIAS>
__global__ __launch_bounds__(256)
void gemm_bf16(const float* __restrict__ Aext, int aOff,
               const float* __restrict__ W,
               const float* __restrict__ bias,
               int cOff, int M, int K) {
    const float* A = rsv(Aext, aOff);
    float* C = g_scratch + cOff;

    __shared__ __align__(16) __nv_bfloat16 sA[128 * ASTRIDE];
    __shared__ __align__(16) __nv_bfloat16 sB[128 * ASTRIDE];

    const int tid = threadIdx.x;
    const int lane = tid & 31;
    const int wid = tid >> 5;
    const int warp_m = wid >> 2;        // 0..1
    const int warp_n = wid & 3;         // 0..3
    const int g = lane >> 2;            // 0..7
    const int tig = lane & 3;           // 0..3
    const int rowBase = blockIdx.x * 128;

    float acc[4][4][4];
#pragma unroll
    for (int mt = 0; mt < 4; mt++)
#pragma unroll
        for (int nt = 0; nt < 4; nt++)
#pragma unroll
            for (int r = 0; r < 4; r++) acc[mt][nt][r] = 0.0f;

    // staging roles
    const int srow = tid >> 1;          // A row / B n (0..127)
    const int shalf = tid & 1;          // col half (16 elements)
    const int aRow = rowBase + srow;
    const bool aValid = (aRow < M);
    const float* aPtr = A + (size_t)aRow * K + shalf * 16;

    // ldmatrix lane addressing
    const int q = lane >> 3;            // quadrant
    const int lr = lane & 7;
    const int arow_l = lr + 8 * (q & 1);        // row within 16
    const int acolB = (q >> 1) * 16;            // byte offset within kstep
    const int brow_l = lr + 8 * (q >> 1);       // n within 16
    const int bcolB = (q & 1) * 16;             // k-half byte offset

    const int nTile = K >> 5;
    for (int kt = 0; kt < nTile; kt++) {
        const int k0 = kt << 5;
        // ---- stage A ----
        {
            float4 v0 = make_float4(0,0,0,0), v1 = v0, v2 = v0, v3 = v0;
            if (aValid) {
                const float4* p = (const float4*)(aPtr + k0);
                v0 = p[0]; v1 = p[1]; v2 = p[2]; v3 = p[3];
                if (RIN) {
                    v0.x=fmaxf(v0.x,0.f); v0.y=fmaxf(v0.y,0.f); v0.z=fmaxf(v0.z,0.f); v0.w=fmaxf(v0.w,0.f);
                    v1.x=fmaxf(v1.x,0.f); v1.y=fmaxf(v1.y,0.f); v1.z=fmaxf(v1.z,0.f); v1.w=fmaxf(v1.w,0.f);
                    v2.x=fmaxf(v2.x,0.f); v2.y=fmaxf(v2.y,0.f); v2.z=fmaxf(v2.z,0.f); v2.w=fmaxf(v2.w,0.f);
                    v3.x=fmaxf(v3.x,0.f); v3.y=fmaxf(v3.y,0.f); v3.z=fmaxf(v3.z,0.f); v3.w=fmaxf(v3.w,0.f);
                }
            }
            uint4 u0, u1;
            u0.x = cvt2(v0.x, v0.y); u0.y = cvt2(v0.z, v0.w);
            u0.z = cvt2(v1.x, v1.y); u0.w = cvt2(v1.z, v1.w);
            u1.x = cvt2(v2.x, v2.y); u1.y = cvt2(v2.z, v2.w);
            u1.z = cvt2(v3.x, v3.y); u1.w = cvt2(v3.z, v3.w);
            uint4* dst = (uint4*)(sA + srow * ASTRIDE + shalf * 16);
            dst[0] = u0; dst[1] = u1;
        }
        // ---- stage B (transpose W) ----
        {
            const float* wp = W + (size_t)(k0 + shalf * 16) * 128 + srow;
            float w[16];
#pragma unroll
            for (int j = 0; j < 16; j++) w[j] = wp[(size_t)j * 128];
            uint4 u0, u1;
            u0.x = cvt2(w[0], w[1]);   u0.y = cvt2(w[2], w[3]);
            u0.z = cvt2(w[4], w[5]);   u0.w = cvt2(w[6], w[7]);
            u1.x = cvt2(w[8], w[9]);   u1.y = cvt2(w[10], w[11]);
            u1.z = cvt2(w[12], w[13]); u1.w = cvt2(w[14], w[15]);
            uint4* dst = (uint4*)(sB + srow * ASTRIDE + shalf * 16);
            dst[0] = u0; dst[1] = u1;
        }
        __syncthreads();

        // ---- compute ----
#pragma unroll
        for (int ks = 0; ks < 2; ks++) {
            uint32_t af[4][4];
#pragma unroll
            for (int mt = 0; mt < 4; mt++) {
                const __nv_bfloat16* p = sA + (warp_m * 64 + mt * 16 + arow_l) * ASTRIDE + ks * 16;
                uint32_t addr = (uint32_t)__cvta_generic_to_shared(p) + acolB;
                asm volatile("ldmatrix.sync.aligned.m8n8.x4.shared.b16 {%0,%1,%2,%3}, [%4];"
                             : "=r"(af[mt][0]), "=r"(af[mt][1]), "=r"(af[mt][2]), "=r"(af[mt][3])
                             : "r"(addr));
            }
            uint32_t bf[4][2];
#pragma unroll
            for (int np = 0; np < 2; np++) {
                const __nv_bfloat16* p = sB + (warp_n * 32 + np * 16 + brow_l) * ASTRIDE + ks * 16;
                uint32_t addr = (uint32_t)__cvta_generic_to_shared(p) + bcolB;
                uint32_t r0, r1, r2, r3;
                asm volatile("ldmatrix.sync.aligned.m8n8.x4.shared.b16 {%0,%1,%2,%3}, [%4];"
                             : "=r"(r0), "=r"(r1), "=r"(r2), "=r"(r3)
                             : "r"(addr));
                bf[np * 2][0] = r0;     bf[np * 2][1] = r1;
                bf[np * 2 + 1][0] = r2; bf[np * 2 + 1][1] = r3;
            }
#pragma unroll
            for (int mt = 0; mt < 4; mt++)
#pragma unroll
                for (int nt = 0; nt < 4; nt++) {
                    asm volatile(
                        "mma.sync.aligned.m16n8k16.row.col.f32.bf16.bf16.f32 "
                        "{%0,%1,%2,%3}, {%4,%5,%6,%7}, {%8,%9}, {%0,%1,%2,%3};"
                        : "+f"(acc[mt][nt][0]), "+f"(acc[mt][nt][1]),
                          "+f"(acc[mt][nt][2]), "+f"(acc[mt][nt][3])
                        : "r"(af[mt][0]), "r"(af[mt][1]), "r"(af[mt][2]), "r"(af[mt][3]),
                          "r"(bf[nt][0]), "r"(bf[nt][1]));
                }
        }
        __syncthreads();
    }

    // ---- epilogue ----
#pragma unroll
    for (int mt = 0; mt < 4; mt++) {
        int row0 = rowBase + warp_m * 64 + mt * 16 + g;
#pragma unroll
        for (int nt = 0; nt < 4; nt++) {
            int col = warp_n * 32 + nt * 8 + tig * 2;
            float b0 = 0.f, b1 = 0.f;
            if (BIAS) { b0 = bias[col]; b1 = bias[col + 1]; }
            float2 v01, v23;
            v01.x = acc[mt][nt][0] + b0; v01.y = acc[mt][nt][1] + b1;
            v23.x = acc[mt][nt][2] + b0; v23.y = acc[mt][nt][3] + b1;
            if (ROUT) {
                v01.x = fmaxf(v01.x, 0.f); v01.y = fmaxf(v01.y, 0.f);
                v23.x = fmaxf(v23.x, 0.f); v23.y = fmaxf(v23.y, 0.f);
            }
            if (row0 < M)     *(float2*)(C + (size_t)row0 * 128 + col) = v01;
            if (row0 + 8 < M) *(float2*)(C + (size_t)(row0 + 8) * 128 + col) = v23;
        }
    }
}

// ---------------------------------------------------------------------------
// GCN aggregation (gather, no atomics): one warp per dst node, unroll 4.
// ---------------------------------------------------------------------------
__global__ __launch_bounds__(256)
void aggregate_kernel(int xwOff, const float* __restrict__ bias,
                      int outOff, int n) {
    const float4* xw4 = (const float4*)(g_scratch + xwOff);
    float4* out4 = (float4*)(g_scratch + outOff);
    int d = (blockIdx.x * blockDim.x + threadIdx.x) >> 5;
    int lane = threadIdx.x & 31;
    if (d >= n) return;

    float di = g_dis[d];
    float sn = di * di;
    float4 b = ((const float4*)bias)[lane];
    float4 x = xw4[(size_t)d * 32 + lane];
    float4 acc;
    acc.x = b.x + sn * x.x; acc.y = b.y + sn * x.y;
    acc.z = b.z + sn * x.z; acc.w = b.w + sn * x.w;

    int i = g_rowptr[d];
    const int end = g_rowptr[d + 1];
    for (; i + 3 < end; i += 4) {
        int s0 = g_csr_src[i],     s1 = g_csr_src[i + 1];
        int s2 = g_csr_src[i + 2], s3 = g_csr_src[i + 3];
        float n0 = g_csr_norm[i],     n1 = g_csr_norm[i + 1];
        float n2 = g_csr_norm[i + 2], n3 = g_csr_norm[i + 3];
        float4 v0 = xw4[(size_t)s0 * 32 + lane];
        float4 v1 = xw4[(size_t)s1 * 32 + lane];
        float4 v2 = xw4[(size_t)s2 * 32 + lane];
        float4 v3 = xw4[(size_t)s3 * 32 + lane];
        acc.x += n0 * v0.x + n1 * v1.x + n2 * v2.x + n3 * v3.x;
        acc.y += n0 * v0.y + n1 * v1.y + n2 * v2.y + n3 * v3.y;
        acc.z += n0 * v0.z + n1 * v1.z + n2 * v2.z + n3 * v3.z;
        acc.w += n0 * v0.w + n1 * v1.w + n2 * v2.w + n3 * v3.w;
    }
    for (; i < end; i++) {
        int s0 = g_csr_src[i];
        float n0 = g_csr_norm[i];
        float4 v0 = xw4[(size_t)s0 * 32 + lane];
        acc.x += n0 * v0.x; acc.y += n0 * v0.y;
        acc.z += n0 * v0.z; acc.w += n0 * v0.w;
    }
    out4[(size_t)d * 32 + lane] = acc;
}

// ---------------------------------------------------------------------------
// Edge classifier, CSR order: one warp per dst node. B[d] row loaded once;
// per in-edge gather A[src], reduce, scatter sigmoid to out[eid].
// ---------------------------------------------------------------------------
__global__ __launch_bounds__(256)
void edge_cls_csr_kernel(int aOff, int bOff,
                         const float* __restrict__ w2,
                         const float* __restrict__ b2,
                         float* __restrict__ out, int n) {
    const float4* Amat = (const float4*)(g_scratch + aOff);
    const float4* Bmat = (const float4*)(g_scratch + bOff);
    int d = (blockIdx.x * blockDim.x + threadIdx.x) >> 5;
    int lane = threadIdx.x & 31;
    if (d >= n) return;

    float4 bv = Bmat[(size_t)d * 32 + lane];
    float4 ww = ((const float4*)w2)[lane];
    const float bb = b2[0];

    int i = g_rowptr[d];
    const int end = g_rowptr[d + 1];
    for (; i + 1 < end; i += 2) {
        int s0 = g_csr_src[i], s1 = g_csr_src[i + 1];
        int e0 = g_csr_eid[i], e1 = g_csr_eid[i + 1];
        float4 a0 = Amat[(size_t)s0 * 32 + lane];
        float4 a1 = Amat[(size_t)s1 * 32 + lane];
        float p0 = fmaxf(a0.x + bv.x, 0.f) * ww.x
                 + fmaxf(a0.y + bv.y, 0.f) * ww.y
                 + fmaxf(a0.z + bv.z, 0.f) * ww.z
                 + fmaxf(a0.w + bv.w, 0.f) * ww.w;
        float p1 = fmaxf(a1.x + bv.x, 0.f) * ww.x
                 + fmaxf(a1.y + bv.y, 0.f) * ww.y
                 + fmaxf(a1.z + bv.z, 0.f) * ww.z
                 + fmaxf(a1.w + bv.w, 0.f) * ww.w;
#pragma unroll
        for (int off = 16; off; off >>= 1) {
            p0 += __shfl_xor_sync(0xffffffffu, p0, off);
            p1 += __shfl_xor_sync(0xffffffffu, p1, off);
        }
        if (lane == 0) out[e0] = 1.0f / (1.0f + __expf(-(p0 + bb)));
        if (lane == 1) out[e1] = 1.0f / (1.0f + __expf(-(p1 + bb)));
    }
    if (i < end) {
        int s0 = g_csr_src[i];
        int e0 = g_csr_eid[i];
        float4 a0 = Amat[(size_t)s0 * 32 + lane];
        float p0 = fmaxf(a0.x + bv.x, 0.f) * ww.x
                 + fmaxf(a0.y + bv.y, 0.f) * ww.y
                 + fmaxf(a0.z + bv.z, 0.f) * ww.z
                 + fmaxf(a0.w + bv.w, 0.f) * ww.w;
#pragma unroll
        for (int off = 16; off; off >>= 1)
            p0 += __shfl_xor_sync(0xffffffffu, p0, off);
        if (lane == 0) out[e0] = 1.0f / (1.0f + __expf(-(p0 + bb)));
    }
}

// ---------------------------------------------------------------------------
extern "C" void kernel_launch(void* const* d_in, const int* in_sizes, int n_in,
                              void* d_out, int out_size) {
    const float* nf      = (const float*)d_in[0];
    const int*   ei      = (const int*)d_in[1];
    const float* enc_w1  = (const float*)d_in[2];
    const float* enc_b1  = (const float*)d_in[3];
    const float* enc_w2  = (const float*)d_in[4];
    const float* enc_b2  = (const float*)d_in[5];
    const float* conv_w1 = (const float*)d_in[6];
    const float* conv_b1 = (const float*)d_in[7];
    const float* conv_w2 = (const float*)d_in[8];
    const float* conv_b2 = (const float*)d_in[9];
    const float* conv_w3 = (const float*)d_in[10];
    const float* conv_b3 = (const float*)d_in[11];
    const float* cls_w1  = (const float*)d_in[12];
    const float* cls_b1  = (const float*)d_in[13];
    const float* cls_w2  = (const float*)d_in[14];
    const float* cls_b2  = (const float*)d_in[15];

    const int n = in_sizes[0] / FDIM;
    const int E = in_sizes[1] / 2;

    const int T = 256;
    const int gm = (n + 127) / 128;
    const int gN = (n + T - 1) / T;
    const int gE = (E + T - 1) / T;
    const int gAgg = (n * 32 + T - 1) / T;
    const int nb = (n + 1023) / 1024;

    // CSR build + normalization
    zero_int_kernel<<<gN, T>>>(n);
    count_kernel<<<gE, T>>>(ei, E);
    dis_kernel<<<gN, T>>>(n);
    scan_phase1<<<nb, 256>>>(n);
    scan_phase2<<<1, 64>>>(nb);
    scan_phase3<<<nb, 256>>>(n, E);
    fill_kernel<<<gE, T>>>(ei, E);

    // node encoder: buf1 = relu(nf@W1+b1e)@W2 + b2e
    gemm_bf16<false, true, true><<<gm, 256>>>(nf, 0, enc_w1, enc_b1, BUF0_OFF, n, FDIM);
    gemm_bf16<false, false, true><<<gm, 256>>>(nullptr, BUF0_OFF, enc_w2, enc_b2, BUF1_OFF, n, H);

    // conv1 (relu deferred to next GEMM input)
    gemm_bf16<false, false, false><<<gm, 256>>>(nullptr, BUF1_OFF, conv_w1, nullptr, BUF0_OFF, n, H);
    aggregate_kernel<<<gAgg, T>>>(BUF0_OFF, conv_b1, BUF2_OFF, n);

    // conv2
    gemm_bf16<true, false, false><<<gm, 256>>>(nullptr, BUF2_OFF, conv_w2, nullptr, BUF0_OFF, n, H);
    aggregate_kernel<<<gAgg, T>>>(BUF0_OFF, conv_b2, BUF1_OFF, n);

    // conv3
    gemm_bf16<true, false, false><<<gm, 256>>>(nullptr, BUF1_OFF, conv_w3, nullptr, BUF0_OFF, n, H);
    aggregate_kernel<<<gAgg, T>>>(BUF0_OFF, conv_b3, BUF2_OFF, n);

    // classifier partials: A = X@W1_top + cls_b1 (buf0), B = X@W1_bot (buf1)
    gemm_bf16<false, false, true><<<gm, 256>>>(nullptr, BUF2_OFF, cls_w1, cls_b1, BUF0_OFF, n, H);
    gemm_bf16<false, false, false><<<gm, 256>>>(nullptr, BUF2_OFF, cls_w1 + 128 * 128, nullptr, BUF1_OFF, n, H);

    // per-edge score in CSR order (B row amortized per dst node)
    edge_cls_csr_kernel<<<gAgg, T>>>(BUF0_OFF, BUF1_OFF, cls_w2, cls_b2, (float*)d_out, n);
}

// round 17
// speedup vs baseline: 1.7241x; 1.0409x over previous
#include <cuda_runtime.h>
#include <cuda_bf16.h>
#include <math.h>
#include <stdint.h>

#define FDIM 256
#define H 128
#define NMAX 50000
#define EMAX 1600000

// Scratch (allocation-free rule: __device__ globals)
#define BUF0_OFF 0
#define BUF1_OFF (NMAX * H)
#define BUF2_OFF (2 * NMAX * H)
__device__ float g_scratch[3 * NMAX * H];
__device__ float g_dis[NMAX];
__device__ int   g_cnt[NMAX];
__device__ int   g_fill[NMAX];
__device__ int   g_rowptr[NMAX + 1];
__device__ int   g_csr_src[EMAX];
__device__ int   g_csr_eid[EMAX];
__device__ float g_csr_norm[EMAX];
__device__ int   g_blocksum[64];
__device__ int   g_blockoff[64];

__device__ __forceinline__ const float* rsv(const float* p, int off) {
    return p ? p : (g_scratch + off);
}

// ---------------------------------------------------------------------------
// CSR build: count -> dis -> 3-phase scan -> fill
// ---------------------------------------------------------------------------
__global__ void zero_int_kernel(int n) {
    int i = blockIdx.x * blockDim.x + threadIdx.x;
    if (i < n) { g_cnt[i] = 0; g_fill[i] = 0; }
}

__global__ void count_kernel(const int* __restrict__ ei, int E) {
    int e = blockIdx.x * blockDim.x + threadIdx.x;
    if (e < E) atomicAdd(&g_cnt[ei[(size_t)E + e]], 1);
}

__global__ void dis_kernel(int n) {
    int i = blockIdx.x * blockDim.x + threadIdx.x;
    if (i < n) g_dis[i] = rsqrtf((float)(g_cnt[i] + 1));  // +1 self loop
}

__global__ void scan_phase1(int n) {
    int t = threadIdx.x;
    int base = blockIdx.x * 1024 + t * 4;
    int s = 0;
#pragma unroll
    for (int j = 0; j < 4; j++) { int i = base + j; if (i < n) s += g_cnt[i]; }
#pragma unroll
    for (int off = 16; off; off >>= 1) s += __shfl_xor_sync(0xffffffffu, s, off);
    __shared__ int wsum[8];
    if ((t & 31) == 0) wsum[t >> 5] = s;
    __syncthreads();
    if (t == 0) {
        int tot = 0;
#pragma unroll
        for (int w = 0; w < 8; w++) tot += wsum[w];
        g_blocksum[blockIdx.x] = tot;
    }
}

__global__ void scan_phase2(int nb) {
    __shared__ int sh[64];
    int t = threadIdx.x;
    int v = (t < nb) ? g_blocksum[t] : 0;
    sh[t] = v;
    __syncthreads();
    for (int off = 1; off < 64; off <<= 1) {
        int tmp = (t >= off) ? sh[t - off] : 0;
        __syncthreads();
        sh[t] += tmp;
        __syncthreads();
    }
    if (t < nb) g_blockoff[t] = sh[t] - v;  // exclusive
}

__global__ void scan_phase3(int n, int E) {
    int t = threadIdx.x;
    int base = blockIdx.x * 1024 + t * 4;
    int v[4]; int s = 0;
#pragma unroll
    for (int j = 0; j < 4; j++) { int i = base + j; v[j] = (i < n) ? g_cnt[i] : 0; s += v[j]; }
    int incl = s;
#pragma unroll
    for (int off = 1; off < 32; off <<= 1) {
        int tmp = __shfl_up_sync(0xffffffffu, incl, off);
        if ((t & 31) >= off) incl += tmp;
    }
    __shared__ int wtot[8];
    __shared__ int woff[8];
    if ((t & 31) == 31) wtot[t >> 5] = incl;
    __syncthreads();
    if (t < 8) {
        int wv = wtot[t];
        int wincl = wv;
#pragma unroll
        for (int off = 1; off < 8; off <<= 1) {
            int tmp = __shfl_up_sync(0x000000ffu, wincl, off);
            if (t >= off) wincl += tmp;
        }
        woff[t] = wincl - wv;
    }
    __syncthreads();
    int prefix = g_blockoff[blockIdx.x] + woff[t >> 5] + (incl - s);
#pragma unroll
    for (int j = 0; j < 4; j++) {
        int i = base + j;
        if (i < n) g_rowptr[i] = prefix;
        prefix += v[j];
    }
    if (blockIdx.x == 0 && t == 0) g_rowptr[n] = E;
}

__global__ void fill_kernel(const int* __restrict__ ei, int E) {
    int e = blockIdx.x * blockDim.x + threadIdx.x;
    if (e >= E) return;
    int s = ei[e];
    int d = ei[(size_t)E + e];
    int pos = g_rowptr[d] + atomicAdd(&g_fill[d], 1);
    g_csr_src[pos] = s;
    g_csr_eid[pos] = e;
    g_csr_norm[pos] = g_dis[s] * g_dis[d];
}

// ---------------------------------------------------------------------------
// bf16 mma.sync GEMM (m16n8k16, fp32 accum). N fixed to 128.
// Block 128x128, BK=32, 256 threads = 8 warps (2m x 4n), warp tile 64x32.
// OBF: write output as bf16 rows (for aggregate-gathered xw buffers).
// ---------------------------------------------------------------------------
#define ASTRIDE 40  // bf16 elements per smem row (80 bytes)

__device__ __forceinline__ unsigned cvt2(float x, float y) {
    __nv_bfloat162 h = __floats2bfloat162_rn(x, y);
    return *reinterpret_cast<unsigned*>(&h);
}

template <bool RIN, bool ROUT, bool BIAS, bool OBF>
__global__ __launch_bounds__(256)
void gemm_bf16(const float* __restrict__ Aext, int aOff,
               const float* __restrict__ W,
               const float* __restrict__ bias,
               int cOff, int M, int K) {
    const float* A = rsv(Aext, aOff);
    float* C = g_scratch + cOff;
    __nv_bfloat16* Cb = (__nv_bfloat16*)(g_scratch + cOff);

    __shared__ __align__(16) __nv_bfloat16 sA[128 * ASTRIDE];
    __shared__ __align__(16) __nv_bfloat16 sB[128 * ASTRIDE];

    const int tid = threadIdx.x;
    const int lane = tid & 31;
    const int wid = tid >> 5;
    const int warp_m = wid >> 2;        // 0..1
    const int warp_n = wid & 3;         // 0..3
    const int g = lane >> 2;            // 0..7
    const int tig = lane & 3;           // 0..3
    const int rowBase = blockIdx.x * 128;

    float acc[4][4][4];
#pragma unroll
    for (int mt = 0; mt < 4; mt++)
#pragma unroll
        for (int nt = 0; nt < 4; nt++)
#pragma unroll
            for (int r = 0; r < 4; r++) acc[mt][nt][r] = 0.0f;

    // staging roles
    const int srow = tid >> 1;          // A row / B n (0..127)
    const int shalf = tid & 1;          // col half (16 elements)
    const int aRow = rowBase + srow;
    const bool aValid = (aRow < M);
    const float* aPtr = A + (size_t)aRow * K + shalf * 16;

    // ldmatrix lane addressing
    const int q = lane >> 3;            // quadrant
    const int lr = lane & 7;
    const int arow_l = lr + 8 * (q & 1);        // row within 16
    const int acolB = (q >> 1) * 16;            // byte offset within kstep
    const int brow_l = lr + 8 * (q >> 1);       // n within 16
    const int bcolB = (q & 1) * 16;             // k-half byte offset

    const int nTile = K >> 5;
    for (int kt = 0; kt < nTile; kt++) {
        const int k0 = kt << 5;
        // ---- stage A ----
        {
            float4 v0 = make_float4(0,0,0,0), v1 = v0, v2 = v0, v3 = v0;
            if (aValid) {
                const float4* p = (const float4*)(aPtr + k0);
                v0 = p[0]; v1 = p[1]; v2 = p[2]; v3 = p[3];
                if (RIN) {
                    v0.x=fmaxf(v0.x,0.f); v0.y=fmaxf(v0.y,0.f); v0.z=fmaxf(v0.z,0.f); v0.w=fmaxf(v0.w,0.f);
                    v1.x=fmaxf(v1.x,0.f); v1.y=fmaxf(v1.y,0.f); v1.z=fmaxf(v1.z,0.f); v1.w=fmaxf(v1.w,0.f);
                    v2.x=fmaxf(v2.x,0.f); v2.y=fmaxf(v2.y,0.f); v2.z=fmaxf(v2.z,0.f); v2.w=fmaxf(v2.w,0.f);
                    v3.x=fmaxf(v3.x,0.f); v3.y=fmaxf(v3.y,0.f); v3.z=fmaxf(v3.z,0.f); v3.w=fmaxf(v3.w,0.f);
                }
            }
            uint4 u0, u1;
            u0.x = cvt2(v0.x, v0.y); u0.y = cvt2(v0.z, v0.w);
            u0.z = cvt2(v1.x, v1.y); u0.w = cvt2(v1.z, v1.w);
            u1.x = cvt2(v2.x, v2.y); u1.y = cvt2(v2.z, v2.w);
            u1.z = cvt2(v3.x, v3.y); u1.w = cvt2(v3.z, v3.w);
            uint4* dst = (uint4*)(sA + srow * ASTRIDE + shalf * 16);
            dst[0] = u0; dst[1] = u1;
        }
        // ---- stage B (transpose W) ----
        {
            const float* wp = W + (size_t)(k0 + shalf * 16) * 128 + srow;
            float w[16];
#pragma unroll
            for (int j = 0; j < 16; j++) w[j] = wp[(size_t)j * 128];
            uint4 u0, u1;
            u0.x = cvt2(w[0], w[1]);   u0.y = cvt2(w[2], w[3]);
            u0.z = cvt2(w[4], w[5]);   u0.w = cvt2(w[6], w[7]);
            u1.x = cvt2(w[8], w[9]);   u1.y = cvt2(w[10], w[11]);
            u1.z = cvt2(w[12], w[13]); u1.w = cvt2(w[14], w[15]);
            uint4* dst = (uint4*)(sB + srow * ASTRIDE + shalf * 16);
            dst[0] = u0; dst[1] = u1;
        }
        __syncthreads();

        // ---- compute ----
#pragma unroll
        for (int ks = 0; ks < 2; ks++) {
            uint32_t af[4][4];
#pragma unroll
            for (int mt = 0; mt < 4; mt++) {
                const __nv_bfloat16* p = sA + (warp_m * 64 + mt * 16 + arow_l) * ASTRIDE + ks * 16;
                uint32_t addr = (uint32_t)__cvta_generic_to_shared(p) + acolB;
                asm volatile("ldmatrix.sync.aligned.m8n8.x4.shared.b16 {%0,%1,%2,%3}, [%4];"
                             : "=r"(af[mt][0]), "=r"(af[mt][1]), "=r"(af[mt][2]), "=r"(af[mt][3])
                             : "r"(addr));
            }
            uint32_t bf[4][2];
#pragma unroll
            for (int np = 0; np < 2; np++) {
                const __nv_bfloat16* p = sB + (warp_n * 32 + np * 16 + brow_l) * ASTRIDE + ks * 16;
                uint32_t addr = (uint32_t)__cvta_generic_to_shared(p) + bcolB;
                uint32_t r0, r1, r2, r3;
                asm volatile("ldmatrix.sync.aligned.m8n8.x4.shared.b16 {%0,%1,%2,%3}, [%4];"
                             : "=r"(r0), "=r"(r1), "=r"(r2), "=r"(r3)
                             : "r"(addr));
                bf[np * 2][0] = r0;     bf[np * 2][1] = r1;
                bf[np * 2 + 1][0] = r2; bf[np * 2 + 1][1] = r3;
            }
#pragma unroll
            for (int mt = 0; mt < 4; mt++)
#pragma unroll
                for (int nt = 0; nt < 4; nt++) {
                    asm volatile(
                        "mma.sync.aligned.m16n8k16.row.col.f32.bf16.bf16.f32 "
                        "{%0,%1,%2,%3}, {%4,%5,%6,%7}, {%8,%9}, {%0,%1,%2,%3};"
                        : "+f"(acc[mt][nt][0]), "+f"(acc[mt][nt][1]),
                          "+f"(acc[mt][nt][2]), "+f"(acc[mt][nt][3])
                        : "r"(af[mt][0]), "r"(af[mt][1]), "r"(af[mt][2]), "r"(af[mt][3]),
                          "r"(bf[nt][0]), "r"(bf[nt][1]));
                }
        }
        __syncthreads();
    }

    // ---- epilogue ----
#pragma unroll
    for (int mt = 0; mt < 4; mt++) {
        int row0 = rowBase + warp_m * 64 + mt * 16 + g;
#pragma unroll
        for (int nt = 0; nt < 4; nt++) {
            int col = warp_n * 32 + nt * 8 + tig * 2;
            float b0 = 0.f, b1 = 0.f;
            if (BIAS) { b0 = bias[col]; b1 = bias[col + 1]; }
            float2 v01, v23;
            v01.x = acc[mt][nt][0] + b0; v01.y = acc[mt][nt][1] + b1;
            v23.x = acc[mt][nt][2] + b0; v23.y = acc[mt][nt][3] + b1;
            if (ROUT) {
                v01.x = fmaxf(v01.x, 0.f); v01.y = fmaxf(v01.y, 0.f);
                v23.x = fmaxf(v23.x, 0.f); v23.y = fmaxf(v23.y, 0.f);
            }
            if (OBF) {
                if (row0 < M)
                    *(unsigned*)(Cb + (size_t)row0 * 128 + col) = cvt2(v01.x, v01.y);
                if (row0 + 8 < M)
                    *(unsigned*)(Cb + (size_t)(row0 + 8) * 128 + col) = cvt2(v23.x, v23.y);
            } else {
                if (row0 < M)     *(float2*)(C + (size_t)row0 * 128 + col) = v01;
                if (row0 + 8 < M) *(float2*)(C + (size_t)(row0 + 8) * 128 + col) = v23;
            }
        }
    }
}

// ---------------------------------------------------------------------------
// GCN aggregation (gather, no atomics): one warp per dst node, unroll 4.
// Gathers bf16 xw rows (LDG.64), accumulates fp32, writes fp32.
// ---------------------------------------------------------------------------
__global__ __launch_bounds__(256)
void aggregate_kernel(int xwOff, const float* __restrict__ bias,
                      int outOff, int n) {
    const uint2* xw2 = (const uint2*)(g_scratch + xwOff);   // bf16 rows: 32 uint2/row
    float4* out4 = (float4*)(g_scratch + outOff);
    int d = (blockIdx.x * blockDim.x + threadIdx.x) >> 5;
    int lane = threadIdx.x & 31;
    if (d >= n) return;

    float di = g_dis[d];
    float sn = di * di;
    float4 b = ((const float4*)bias)[lane];

    float4 acc;
    {
        uint2 u = xw2[(size_t)d * 32 + lane];
        float2 f0 = __bfloat1622float2(*reinterpret_cast<__nv_bfloat162*>(&u.x));
        float2 f1 = __bfloat1622float2(*reinterpret_cast<__nv_bfloat162*>(&u.y));
        acc.x = b.x + sn * f0.x; acc.y = b.y + sn * f0.y;
        acc.z = b.z + sn * f1.x; acc.w = b.w + sn * f1.y;
    }

    int i = g_rowptr[d];
    const int end = g_rowptr[d + 1];
    for (; i + 3 < end; i += 4) {
        int s0 = g_csr_src[i],     s1 = g_csr_src[i + 1];
        int s2 = g_csr_src[i + 2], s3 = g_csr_src[i + 3];
        float n0 = g_csr_norm[i],     n1 = g_csr_norm[i + 1];
        float n2 = g_csr_norm[i + 2], n3 = g_csr_norm[i + 3];
        // batch all gathers before converting (preserve MLP)
        uint2 u0 = xw2[(size_t)s0 * 32 + lane];
        uint2 u1 = xw2[(size_t)s1 * 32 + lane];
        uint2 u2 = xw2[(size_t)s2 * 32 + lane];
        uint2 u3 = xw2[(size_t)s3 * 32 + lane];
        float2 a0 = __bfloat1622float2(*reinterpret_cast<__nv_bfloat162*>(&u0.x));
        float2 b0v = __bfloat1622float2(*reinterpret_cast<__nv_bfloat162*>(&u0.y));
        float2 a1 = __bfloat1622float2(*reinterpret_cast<__nv_bfloat162*>(&u1.x));
        float2 b1v = __bfloat1622float2(*reinterpret_cast<__nv_bfloat162*>(&u1.y));
        float2 a2 = __bfloat1622float2(*reinterpret_cast<__nv_bfloat162*>(&u2.x));
        float2 b2v = __bfloat1622float2(*reinterpret_cast<__nv_bfloat162*>(&u2.y));
        float2 a3 = __bfloat1622float2(*reinterpret_cast<__nv_bfloat162*>(&u3.x));
        float2 b3v = __bfloat1622float2(*reinterpret_cast<__nv_bfloat162*>(&u3.y));
        acc.x += n0 * a0.x + n1 * a1.x + n2 * a2.x + n3 * a3.x;
        acc.y += n0 * a0.y + n1 * a1.y + n2 * a2.y + n3 * a3.y;
        acc.z += n0 * b0v.x + n1 * b1v.x + n2 * b2v.x + n3 * b3v.x;
        acc.w += n0 * b0v.y + n1 * b1v.y + n2 * b2v.y + n3 * b3v.y;
    }
    for (; i < end; i++) {
        int s0 = g_csr_src[i];
        float n0 = g_csr_norm[i];
        uint2 u0 = xw2[(size_t)s0 * 32 + lane];
        float2 a0 = __bfloat1622float2(*reinterpret_cast<__nv_bfloat162*>(&u0.x));
        float2 b0v = __bfloat1622float2(*reinterpret_cast<__nv_bfloat162*>(&u0.y));
        acc.x += n0 * a0.x; acc.y += n0 * a0.y;
        acc.z += n0 * b0v.x; acc.w += n0 * b0v.y;
    }
    out4[(size_t)d * 32 + lane] = acc;
}

// ---------------------------------------------------------------------------
// Edge classifier, CSR order: one warp per dst node. B[d] row loaded once;
// per in-edge gather A[src], reduce, scatter sigmoid to out[eid].  (fp32)
// ---------------------------------------------------------------------------
__global__ __launch_bounds__(256)
void edge_cls_csr_kernel(int aOff, int bOff,
                         const float* __restrict__ w2,
                         const float* __restrict__ b2,
                         float* __restrict__ out, int n) {
    const float4* Amat = (const float4*)(g_scratch + aOff);
    const float4* Bmat = (const float4*)(g_scratch + bOff);
    int d = (blockIdx.x * blockDim.x + threadIdx.x) >> 5;
    int lane = threadIdx.x & 31;
    if (d >= n) return;

    float4 bv = Bmat[(size_t)d * 32 + lane];
    float4 ww = ((const float4*)w2)[lane];
    const float bb = b2[0];

    int i = g_rowptr[d];
    const int end = g_rowptr[d + 1];
    for (; i + 1 < end; i += 2) {
        int s0 = g_csr_src[i], s1 = g_csr_src[i + 1];
        int e0 = g_csr_eid[i], e1 = g_csr_eid[i + 1];
        float4 a0 = Amat[(size_t)s0 * 32 + lane];
        float4 a1 = Amat[(size_t)s1 * 32 + lane];
        float p0 = fmaxf(a0.x + bv.x, 0.f) * ww.x
                 + fmaxf(a0.y + bv.y, 0.f) * ww.y
                 + fmaxf(a0.z + bv.z, 0.f) * ww.z
                 + fmaxf(a0.w + bv.w, 0.f) * ww.w;
        float p1 = fmaxf(a1.x + bv.x, 0.f) * ww.x
                 + fmaxf(a1.y + bv.y, 0.f) * ww.y
                 + fmaxf(a1.z + bv.z, 0.f) * ww.z
                 + fmaxf(a1.w + bv.w, 0.f) * ww.w;
#pragma unroll
        for (int off = 16; off; off >>= 1) {
            p0 += __shfl_xor_sync(0xffffffffu, p0, off);
            p1 += __shfl_xor_sync(0xffffffffu, p1, off);
        }
        if (lane == 0) out[e0] = 1.0f / (1.0f + __expf(-(p0 + bb)));
        if (lane == 1) out[e1] = 1.0f / (1.0f + __expf(-(p1 + bb)));
    }
    if (i < end) {
        int s0 = g_csr_src[i];
        int e0 = g_csr_eid[i];
        float4 a0 = Amat[(size_t)s0 * 32 + lane];
        float p0 = fmaxf(a0.x + bv.x, 0.f) * ww.x
                 + fmaxf(a0.y + bv.y, 0.f) * ww.y
                 + fmaxf(a0.z + bv.z, 0.f) * ww.z
                 + fmaxf(a0.w + bv.w, 0.f) * ww.w;
#pragma unroll
        for (int off = 16; off; off >>= 1)
            p0 += __shfl_xor_sync(0xffffffffu, p0, off);
        if (lane == 0) out[e0] = 1.0f / (1.0f + __expf(-(p0 + bb)));
    }
}

// ---------------------------------------------------------------------------
extern "C" void kernel_launch(void* const* d_in, const int* in_sizes, int n_in,
                              void* d_out, int out_size) {
    const float* nf      = (const float*)d_in[0];
    const int*   ei      = (const int*)d_in[1];
    const float* enc_w1  = (const float*)d_in[2];
    const float* enc_b1  = (const float*)d_in[3];
    const float* enc_w2  = (const float*)d_in[4];
    const float* enc_b2  = (const float*)d_in[5];
    const float* conv_w1 = (const float*)d_in[6];
    const float* conv_b1 = (const float*)d_in[7];
    const float* conv_w2 = (const float*)d_in[8];
    const float* conv_b2 = (const float*)d_in[9];
    const float* conv_w3 = (const float*)d_in[10];
    const float* conv_b3 = (const float*)d_in[11];
    const float* cls_w1  = (const float*)d_in[12];
    const float* cls_b1  = (const float*)d_in[13];
    const float* cls_w2  = (const float*)d_in[14];
    const float* cls_b2  = (const float*)d_in[15];

    const int n = in_sizes[0] / FDIM;
    const int E = in_sizes[1] / 2;

    const int T = 256;
    const int gm = (n + 127) / 128;
    const int gN = (n + T - 1) / T;
    const int gE = (E + T - 1) / T;
    const int gAgg = (n * 32 + T - 1) / T;
    const int nb = (n + 1023) / 1024;

    // CSR build + normalization
    zero_int_kernel<<<gN, T>>>(n);
    count_kernel<<<gE, T>>>(ei, E);
    dis_kernel<<<gN, T>>>(n);
    scan_phase1<<<nb, 256>>>(n);
    scan_phase2<<<1, 64>>>(nb);
    scan_phase3<<<nb, 256>>>(n, E);
    fill_kernel<<<gE, T>>>(ei, E);

    // node encoder: buf1 = relu(nf@W1+b1e)@W2 + b2e   (fp32)
    gemm_bf16<false, true, true, false><<<gm, 256>>>(nf, 0, enc_w1, enc_b1, BUF0_OFF, n, FDIM);
    gemm_bf16<false, false, true, false><<<gm, 256>>>(nullptr, BUF0_OFF, enc_w2, enc_b2, BUF1_OFF, n, H);

    // conv1: xw bf16 -> BUF0; aggregate -> BUF2 (fp32)
    gemm_bf16<false, false, false, true><<<gm, 256>>>(nullptr, BUF1_OFF, conv_w1, nullptr, BUF0_OFF, n, H);
    aggregate_kernel<<<gAgg, T>>>(BUF0_OFF, conv_b1, BUF2_OFF, n);

    // conv2: input relu(BUF2) fp32; xw bf16 -> BUF0; aggregate -> BUF1 (fp32)
    gemm_bf16<true, false, false, true><<<gm, 256>>>(nullptr, BUF2_OFF, conv_w2, nullptr, BUF0_OFF, n, H);
    aggregate_kernel<<<gAgg, T>>>(BUF0_OFF, conv_b2, BUF1_OFF, n);

    // conv3: input relu(BUF1) fp32; xw bf16 -> BUF0; aggregate -> BUF2 (fp32)
    gemm_bf16<true, false, false, true><<<gm, 256>>>(nullptr, BUF1_OFF, conv_w3, nullptr, BUF0_OFF, n, H);
    aggregate_kernel<<<gAgg, T>>>(BUF0_OFF, conv_b3, BUF2_OFF, n);

    // classifier partials (fp32): A = X@W1_top + cls_b1 -> BUF0, B = X@W1_bot -> BUF1
    gemm_bf16<false, false, true, false><<<gm, 256>>>(nullptr, BUF2_OFF, cls_w1, cls_b1, BUF0_OFF, n, H);
    gemm_bf16<false, false, false, false><<<gm, 256>>>(nullptr, BUF2_OFF, cls_w1 + 128 * 128, nullptr, BUF1_OFF, n, H);

    // per-edge score in CSR order (B row amortized per dst node)
    edge_cls_csr_kernel<<<gAgg, T>>>(BUF0_OFF, BUF1_OFF, cls_w2, cls_b2, (float*)d_out, n);
}